// round 15
// baseline (speedup 1.0000x reference)
#include <cuda_runtime.h>
#include <cuda_bf16.h>
#include <mma.h>
#include <cstdint>

using namespace nvcuda;
typedef __nv_bfloat16 bf16;

#define BB    2
#define LL    4096
#define DM    1024
#define DS    16
#define DI    2048
#define DTR   64
#define MM    (BB*LL)          // 8192
#define CH    128
#define NCH   (LL/CH)          // 32

// ---------------- scratch (device globals) ---------------------------------
__device__ bf16  g_xz [ (size_t)MM * (2*DI) ];    // 8192x4096 (xs | z) bf16
__device__ float g_dbl[ (size_t)MM * 96 ];        // dt_lo64 | B16 | C16  fp32
__device__ float g_dblp[ (size_t)4 * MM * 96 ];   // split-K partials
__device__ bf16  g_dt [ (size_t)MM * DI ];
__device__ bf16  g_xnb [ (size_t)MM * DM ];
__device__ bf16  g_xcb [ (size_t)MM * DI ];
__device__ bf16  g_dtlo[ (size_t)MM * DTR ];
__device__ bf16  g_yb  [ (size_t)MM * DI ];
__device__ bf16  g_Winb [ (size_t)(2*DI) * DM ];
__device__ bf16  g_Wxpb [ (size_t)96 * DI ];
__device__ bf16  g_Wdtb [ (size_t)DI * DTR ];
__device__ bf16  g_Woutb[ (size_t)DM * DI ];
// scan chunk buffers, layout idx(b,ch,s,d) = ((b*NCH+ch)*DS+s)*DI + d
__device__ float g_P [ (size_t)BB * NCH * DS * DI ];
__device__ float g_U [ (size_t)BB * NCH * DS * DI ];
__device__ float g_H [ (size_t)BB * NCH * DS * DI ];

#define LOG2E 1.4426950408889634f

// ======================= helpers ============================================
__device__ __forceinline__ void cp_async16(uint32_t saddr, const void* gptr) {
    asm volatile("cp.async.cg.shared.global [%0], [%1], 16;\n" :: "r"(saddr), "l"(gptr));
}
__device__ __forceinline__ void ldsm_x4(uint32_t* r, uint32_t addr) {
    asm volatile("ldmatrix.sync.aligned.m8n8.x4.shared.b16 {%0,%1,%2,%3}, [%4];"
        : "=r"(r[0]), "=r"(r[1]), "=r"(r[2]), "=r"(r[3]) : "r"(addr));
}
__device__ __forceinline__ void mma16816(float* d, const uint32_t* a, uint32_t b0, uint32_t b1) {
    asm volatile("mma.sync.aligned.m16n8k16.row.col.f32.bf16.bf16.f32 "
        "{%0,%1,%2,%3}, {%4,%5,%6,%7}, {%8,%9}, {%0,%1,%2,%3};"
        : "+f"(d[0]), "+f"(d[1]), "+f"(d[2]), "+f"(d[3])
        : "r"(a[0]), "r"(a[1]), "r"(a[2]), "r"(a[3]), "r"(b0), "r"(b1));
}
__device__ __forceinline__ float fast_softplus(float v) {
    return (v > 15.f) ? v : __logf(1.f + __expf(v));
}
__device__ __forceinline__ float4 ld_bf16x4(const bf16* p) {
    __nv_bfloat162 a = ((const __nv_bfloat162*)p)[0];
    __nv_bfloat162 b = ((const __nv_bfloat162*)p)[1];
    return make_float4(__low2float(a), __high2float(a), __low2float(b), __high2float(b));
}

// ======================= mma.sync GEMM ======================================
//  CTA 128x128, BK=64, 3-stage, 128 threads, warp tile 64x64 (2x2 warp grid).
//  EPI: 1 fp32 out + residual aux[MxN];  2 bf16 out softplus(v+aux[col]);
//  EPI: 3 bf16 out plain.
template<int EPI>
__global__ __launch_bounds__(128, 2)
void mma_gemm_kernel(const bf16* __restrict__ A, int lda,
                     const bf16* __restrict__ W, int ldb,
                     void* __restrict__ Cv, int ldc,
                     int K, const float* __restrict__ aux)
{
    constexpr int BM = 128, BN = 128, BK = 64, SP = 72, NS = 3;
    constexpr int ASZ = BM * SP;
    constexpr int SSZ = (BM + BN) * SP;         // 36864 B/stage

    extern __shared__ bf16 sm2[];
    const int tid  = threadIdx.x;
    const int lane = tid & 31;
    const int wid  = tid >> 5;                  // 0..3
    const int wm   = wid >> 1;                  // 0..1 -> 64 rows
    const int wn   = wid & 1;                   // 0..1 -> 64 cols
    const int bm   = blockIdx.y * BM;
    const int bn   = blockIdx.x * BN;

    auto prefetch = [&](int s, int kt) {
        const int k0 = kt * BK;
        uint32_t base = (uint32_t)__cvta_generic_to_shared(sm2 + s * SSZ);
        #pragma unroll
        for (int i = 0; i < 8; i++) {               // A: 1024 x 16B chunks
            int e = i * 128 + tid;
            int r = e >> 3, c = e & 7;
            cp_async16(base + (r * SP + c * 8) * 2,
                       A + (size_t)(bm + r) * lda + k0 + c * 8);
        }
        uint32_t baseB = base + ASZ * 2;
        #pragma unroll
        for (int i = 0; i < 8; i++) {               // B: 1024 x 16B chunks
            int e = i * 128 + tid;
            int r = e >> 3, c = e & 7;
            cp_async16(baseB + (r * SP + c * 8) * 2,
                       W + (size_t)(bn + r) * ldb + k0 + c * 8);
        }
    };

    float acc[4][8][4];
    #pragma unroll
    for (int i = 0; i < 4; i++)
        #pragma unroll
        for (int j = 0; j < 8; j++)
            #pragma unroll
            for (int e = 0; e < 4; e++) acc[i][j][e] = 0.f;

    const int T = K / BK;
    #pragma unroll
    for (int s = 0; s < NS - 1; s++) {
        if (s < T) prefetch(s, s);
        asm volatile("cp.async.commit_group;\n");
    }

    for (int t = 0; t < T; t++) {
        int tn = t + NS - 1;
        if (tn < T) prefetch(tn % NS, tn);
        asm volatile("cp.async.commit_group;\n");
        asm volatile("cp.async.wait_group %0;\n" :: "n"(NS - 1));
        __syncthreads();

        uint32_t abase = (uint32_t)__cvta_generic_to_shared(sm2 + (t % NS) * SSZ);
        uint32_t bbase = abase + ASZ * 2;
        const int half = lane >> 4;
        #pragma unroll
        for (int k16 = 0; k16 < 4; k16++) {
            uint32_t af[4][4], bfr[4][4];
            #pragma unroll
            for (int i = 0; i < 4; i++) {
                int row = wm * 64 + i * 16 + (lane & 15);
                ldsm_x4(af[i], abase + (row * SP + (k16 * 2 + half) * 8) * 2);
            }
            #pragma unroll
            for (int jp = 0; jp < 4; jp++) {
                int row = wn * 64 + jp * 16 + (lane & 15);
                ldsm_x4(bfr[jp], bbase + (row * SP + (k16 * 2 + half) * 8) * 2);
            }
            #pragma unroll
            for (int i = 0; i < 4; i++)
                #pragma unroll
                for (int jp = 0; jp < 4; jp++) {
                    mma16816(acc[i][2*jp],   af[i], bfr[jp][0], bfr[jp][2]);
                    mma16816(acc[i][2*jp+1], af[i], bfr[jp][1], bfr[jp][3]);
                }
        }
        __syncthreads();
    }

    const int r0 = bm + wm * 64 + (lane >> 2);
    const int c0 = bn + wn * 64 + (lane & 3) * 2;
    #pragma unroll
    for (int i = 0; i < 4; i++) {
        #pragma unroll
        for (int j = 0; j < 8; j++) {
            int r = r0 + i * 16;
            int c = c0 + j * 8;
            float v0 = acc[i][j][0], v1 = acc[i][j][1];
            float v2 = acc[i][j][2], v3 = acc[i][j][3];
            if (EPI == 1) {
                float* C = (float*)Cv;
                const float2 a0 = *(const float2*)(aux + (size_t)r * ldc + c);
                const float2 a1 = *(const float2*)(aux + (size_t)(r+8) * ldc + c);
                v0 += a0.x; v1 += a0.y; v2 += a1.x; v3 += a1.y;
                *(float2*)(C + (size_t)r * ldc + c)     = make_float2(v0, v1);
                *(float2*)(C + (size_t)(r+8) * ldc + c) = make_float2(v2, v3);
            } else if (EPI == 2) {
                bf16* C = (bf16*)Cv;
                float b0 = aux[c], b1 = aux[c+1];
                v0 = fast_softplus(v0 + b0);
                v1 = fast_softplus(v1 + b1);
                v2 = fast_softplus(v2 + b0);
                v3 = fast_softplus(v3 + b1);
                *(__nv_bfloat162*)(C + (size_t)r * ldc + c)     = __floats2bfloat162_rn(v0, v1);
                *(__nv_bfloat162*)(C + (size_t)(r+8) * ldc + c) = __floats2bfloat162_rn(v2, v3);
            } else {
                bf16* C = (bf16*)Cv;
                *(__nv_bfloat162*)(C + (size_t)r * ldc + c)     = __floats2bfloat162_rn(v0, v1);
                *(__nv_bfloat162*)(C + (size_t)(r+8) * ldc + c) = __floats2bfloat162_rn(v2, v3);
            }
        }
    }
}

// ---------------- fp32 -> bf16 converts ------------------------------------
__global__ void f2bf_kernel(const float* __restrict__ src, bf16* __restrict__ dst, int n)
{
    int i = (blockIdx.x * 256 + threadIdx.x) * 4;
    if (i < n) {
        float4 v = *(const float4*)(src + i);
        __nv_bfloat162* d = (__nv_bfloat162*)(dst + i);
        d[0] = __floats2bfloat162_rn(v.x, v.y);
        d[1] = __floats2bfloat162_rn(v.z, v.w);
    }
}

__global__ void f2bf3_kernel(const float* __restrict__ s0, bf16* __restrict__ d0, int n0,
                             const float* __restrict__ s1, bf16* __restrict__ d1, int n1,
                             const float* __restrict__ s2, bf16* __restrict__ d2, int n2)
{
    int i = (blockIdx.x * 256 + threadIdx.x) * 4;
    const float* s; bf16* d; int off;
    if (i < n0)                { s = s0; d = d0; off = i; }
    else if (i < n0 + n1)      { s = s1; d = d1; off = i - n0; }
    else if (i < n0 + n1 + n2) { s = s2; d = d2; off = i - n0 - n1; }
    else return;
    float4 v = *(const float4*)(s + off);
    __nv_bfloat162* dd = (__nv_bfloat162*)(d + off);
    dd[0] = __floats2bfloat162_rn(v.x, v.y);
    dd[1] = __floats2bfloat162_rn(v.z, v.w);
}

// ---------------- layernorm -> bf16 ----------------------------------------
__global__ void layernorm_kernel(const float* __restrict__ x,
                                 const float* __restrict__ g,
                                 const float* __restrict__ b,
                                 bf16* __restrict__ o)
{
    __shared__ float red[64];
    int row = blockIdx.x;
    int t = threadIdx.x;
    const float4* xr = (const float4*)(x + (size_t)row * DM);
    float4 v = xr[t];
    float s = v.x + v.y + v.z + v.w;
    float q = v.x*v.x + v.y*v.y + v.z*v.z + v.w*v.w;
    #pragma unroll
    for (int off = 16; off; off >>= 1) {
        s += __shfl_xor_sync(0xffffffffu, s, off);
        q += __shfl_xor_sync(0xffffffffu, q, off);
    }
    if ((t & 31) == 0) { red[t >> 5] = s; red[32 + (t >> 5)] = q; }
    __syncthreads();
    if (t < 32) {
        float s2 = (t < 8) ? red[t]      : 0.f;
        float q2 = (t < 8) ? red[32 + t] : 0.f;
        #pragma unroll
        for (int off = 4; off; off >>= 1) {
            s2 += __shfl_xor_sync(0xffffffffu, s2, off);
            q2 += __shfl_xor_sync(0xffffffffu, q2, off);
        }
        if (t == 0) { red[0] = s2; red[1] = q2; }
    }
    __syncthreads();
    float mu  = red[0] * (1.f / DM);
    float var = red[1] * (1.f / DM) - mu * mu;
    float inv = rsqrtf(var + 1e-5f);
    float4 gv = ((const float4*)g)[t];
    float4 bv = ((const float4*)b)[t];
    __nv_bfloat162* op = (__nv_bfloat162*)(o + (size_t)row * DM + t * 4);
    op[0] = __floats2bfloat162_rn((v.x - mu)*inv*gv.x + bv.x, (v.y - mu)*inv*gv.y + bv.y);
    op[1] = __floats2bfloat162_rn((v.z - mu)*inv*gv.z + bv.z, (v.w - mu)*inv*gv.w + bv.w);
}

// ---------------- bf16 wmma GEMM (W_xp, split-K via blockIdx.z) ------------
#define STAGES 3
#define SPAD   40

template<int BM, int BN, int WGM, int WGN>
__global__ __launch_bounds__(WGM*WGN*32)
void hgemm_kernel(const bf16* __restrict__ A, int lda,
                  const bf16* __restrict__ W, int ldb,
                  float* __restrict__ C, int ldc,
                  int N, int K,
                  int zk_off, size_t zc_off)
{
    constexpr int TM = BM / WGM;
    constexpr int TN = BN / WGN;
    constexpr int MF = TM / 16;
    constexpr int NF = TN / 16;
    constexpr int NT = WGM * WGN * 32;
    constexpr int SSZ = (BM + BN) * SPAD;

    extern __shared__ bf16 smh[];

    A += (size_t)blockIdx.z * zk_off;
    W += (size_t)blockIdx.z * zk_off;
    C += (size_t)blockIdx.z * zc_off;

    int tid = threadIdx.x;
    int wid = tid >> 5;
    int wm  = wid / WGN;
    int wn  = wid % WGN;
    int bm  = blockIdx.y * BM;
    int bn  = blockIdx.x * BN;

    auto prefetch = [&](int p, int k0) {
        uint32_t sbase = (uint32_t)__cvta_generic_to_shared(smh + p * SSZ);
        #pragma unroll
        for (int i = 0; i < (BM * 4) / NT; i++) {
            int e = i * NT + tid;
            int row = e >> 2, c8 = (e & 3) * 8;
            cp_async16(sbase + (row * SPAD + c8) * 2,
                       A + (size_t)(bm + row) * lda + k0 + c8);
        }
        uint32_t sbase2 = sbase + BM * SPAD * 2;
        #pragma unroll
        for (int i = 0; i < (BN * 4) / NT; i++) {
            int e = i * NT + tid;
            int row = e >> 2, c8 = (e & 3) * 8;
            int n = bn + row; if (n >= N) n = N - 1;
            cp_async16(sbase2 + (row * SPAD + c8) * 2,
                       W + (size_t)n * ldb + k0 + c8);
        }
    };

    wmma::fragment<wmma::accumulator, 16, 16, 16, float> acc[MF][NF];
    #pragma unroll
    for (int i = 0; i < MF; i++)
        #pragma unroll
        for (int j = 0; j < NF; j++) wmma::fill_fragment(acc[i][j], 0.f);

    int T = K / 32;
    #pragma unroll
    for (int s = 0; s < STAGES - 1; s++) {
        if (s < T) prefetch(s, s * 32);
        asm volatile("cp.async.commit_group;\n");
    }

    for (int t = 0; t < T; t++) {
        asm volatile("cp.async.wait_group %0;\n" :: "n"(STAGES - 2));
        __syncthreads();

        int pn = t + STAGES - 1;
        if (pn < T) prefetch(pn % STAGES, pn * 32);
        asm volatile("cp.async.commit_group;\n");

        const bf16* As = smh + (t % STAGES) * SSZ;
        const bf16* Ws = As + BM * SPAD;
        #pragma unroll
        for (int ks = 0; ks < 32; ks += 16) {
            wmma::fragment<wmma::matrix_a, 16, 16, 16, bf16, wmma::row_major> af[MF];
            wmma::fragment<wmma::matrix_b, 16, 16, 16, bf16, wmma::col_major> bff[NF];
            #pragma unroll
            for (int i = 0; i < MF; i++)
                wmma::load_matrix_sync(af[i], As + (wm * TM + i * 16) * SPAD + ks, SPAD);
            #pragma unroll
            for (int j = 0; j < NF; j++)
                wmma::load_matrix_sync(bff[j], Ws + (wn * TN + j * 16) * SPAD + ks, SPAD);
            #pragma unroll
            for (int i = 0; i < MF; i++)
                #pragma unroll
                for (int j = 0; j < NF; j++)
                    wmma::mma_sync(acc[i][j], af[i], bff[j], acc[i][j]);
        }
        __syncthreads();
    }

    #pragma unroll
    for (int i = 0; i < MF; i++) {
        int r0 = bm + wm * TM + i * 16;
        #pragma unroll
        for (int j = 0; j < NF; j++) {
            int c0 = bn + wn * TN + j * 16;
            if (c0 < N) {
                wmma::store_matrix_sync(C + (size_t)r0 * ldc + c0, acc[i][j], ldc, wmma::mem_row_major);
            }
        }
    }
}

// ---------------- split-K reduce + dtlo extraction -------------------------
__global__ void dbl_reduce_kernel(const float* __restrict__ dblp,
                                  float* __restrict__ dbl,
                                  bf16* __restrict__ dtlo)
{
    int idx = blockIdx.x * 256 + threadIdx.x;   // over MM*96
    const size_t STR = (size_t)MM * 96;
    float v = dblp[idx] + dblp[idx + STR] + dblp[idx + 2*STR] + dblp[idx + 3*STR];
    dbl[idx] = v;
    int m = idx / 96, c = idx - m * 96;
    if (c < DTR) dtlo[m * DTR + c] = __float2bfloat16(v);
}

// ---------------- causal depthwise conv (DC=4) + silu, 4 channels/thread ---
__global__ void conv_silu_kernel(const bf16* __restrict__ xz,
                                 const float* __restrict__ cw,
                                 const float* __restrict__ cb,
                                 bf16* __restrict__ xcb)
{
    int idx = blockIdx.x * 256 + threadIdx.x;      // over M*DI/4
    int dq = idx & (DI/4 - 1);
    int m  = idx >> 9;
    int l  = m & (LL - 1);
    int d  = dq * 4;
    const bf16* p = xz + (size_t)m * (2*DI) + d;
    float4 w0 = *(const float4*)(cw + (d+0) * 4);
    float4 w1 = *(const float4*)(cw + (d+1) * 4);
    float4 w2 = *(const float4*)(cw + (d+2) * 4);
    float4 w3 = *(const float4*)(cw + (d+3) * 4);
    float4 bias = *(const float4*)(cb + d);
    float4 v = ld_bf16x4(p);
    float a0 = fmaf(w0.w, v.x, bias.x);
    float a1 = fmaf(w1.w, v.y, bias.y);
    float a2 = fmaf(w2.w, v.z, bias.z);
    float a3 = fmaf(w3.w, v.w, bias.w);
    if (l >= 1) { float4 u = ld_bf16x4(p - 2*DI);
        a0 = fmaf(w0.z, u.x, a0); a1 = fmaf(w1.z, u.y, a1);
        a2 = fmaf(w2.z, u.z, a2); a3 = fmaf(w3.z, u.w, a3); }
    if (l >= 2) { float4 u = ld_bf16x4(p - 4*DI);
        a0 = fmaf(w0.y, u.x, a0); a1 = fmaf(w1.y, u.y, a1);
        a2 = fmaf(w2.y, u.z, a2); a3 = fmaf(w3.y, u.w, a3); }
    if (l >= 3) { float4 u = ld_bf16x4(p - 6*DI);
        a0 = fmaf(w0.x, u.x, a0); a1 = fmaf(w1.x, u.y, a1);
        a2 = fmaf(w2.x, u.z, a2); a3 = fmaf(w3.x, u.w, a3); }
    float r0 = a0 / (1.f + __expf(-a0));
    float r1 = a1 / (1.f + __expf(-a1));
    float r2 = a2 / (1.f + __expf(-a2));
    float r3 = a3 / (1.f + __expf(-a3));
    __nv_bfloat162* ob = (__nv_bfloat162*)(xcb + (size_t)m * DI + d);
    ob[0] = __floats2bfloat162_rn(r0, r1);
    ob[1] = __floats2bfloat162_rn(r2, r3);
}

// =============== chunked selective scan (16 states per thread) ==============
__global__ __launch_bounds__(256)
void scan_p1_kernel(const bf16* __restrict__ dt,
                    const bf16* __restrict__ xc,
                    const float* __restrict__ dbl,
                    const float* __restrict__ A_log,
                    float* __restrict__ P, float* __restrict__ U)
{
    int gid = blockIdx.x * 256 + threadIdx.x;   // BB*NCH*DI = 131072
    int d  = gid & (DI - 1);
    int ch = (gid >> 11) & (NCH - 1);
    int b  = gid >> 16;

    float A2[DS], Pv[DS], Uv[DS];
    #pragma unroll
    for (int s = 0; s < DS; s++) {
        A2[s] = -__expf(A_log[d * DS + s]) * LOG2E;
        Pv[s] = 1.f; Uv[s] = 0.f;
    }
    bool fastp = true;
    #pragma unroll
    for (int s = 0; s < DS; s++)
        fastp = fastp && (fabsf(A2[s] - (float)(s + 1) * A2[0]) <= 1e-4f * fabsf(A2[s]));

    size_t mbase = (size_t)b * LL + ch * CH;
    if (fastp) {
        float A20 = A2[0];
        for (int l = 0; l < CH; l++) {
            size_t m = mbase + l;
            float dtv = __bfloat162float(dt[m * DI + d]);
            float xv  = __bfloat162float(xc[m * DI + d]);
            float dx  = dtv * xv;
            const float4* Bp = (const float4*)(dbl + m * 96 + DTR);
            float4 B0 = Bp[0], B1 = Bp[1], B2 = Bp[2], B3 = Bp[3];
            float Bv[DS] = {B0.x,B0.y,B0.z,B0.w, B1.x,B1.y,B1.z,B1.w,
                            B2.x,B2.y,B2.z,B2.w, B3.x,B3.y,B3.z,B3.w};
            float a1 = exp2f(dtv * A20);
            float as = a1;
            #pragma unroll
            for (int s = 0; s < DS; s++) {
                Pv[s] *= as;
                Uv[s] = fmaf(as, Uv[s], dx * Bv[s]);
                as *= a1;
            }
        }
    } else {
        for (int l = 0; l < CH; l++) {
            size_t m = mbase + l;
            float dtv = __bfloat162float(dt[m * DI + d]);
            float xv  = __bfloat162float(xc[m * DI + d]);
            float dx  = dtv * xv;
            const float4* Bp = (const float4*)(dbl + m * 96 + DTR);
            float4 B0 = Bp[0], B1 = Bp[1], B2 = Bp[2], B3 = Bp[3];
            float Bv[DS] = {B0.x,B0.y,B0.z,B0.w, B1.x,B1.y,B1.z,B1.w,
                            B2.x,B2.y,B2.z,B2.w, B3.x,B3.y,B3.z,B3.w};
            #pragma unroll
            for (int s = 0; s < DS; s++) {
                float a = exp2f(dtv * A2[s]);
                Pv[s] *= a;
                Uv[s] = fmaf(a, Uv[s], dx * Bv[s]);
            }
        }
    }
    size_t base = ((size_t)(b * NCH + ch) * DS) * DI + d;
    #pragma unroll
    for (int s = 0; s < DS; s++) {
        P[base + (size_t)s * DI] = Pv[s];
        U[base + (size_t)s * DI] = Uv[s];
    }
}

__global__ void scan_p2_kernel(const float* __restrict__ P,
                               const float* __restrict__ U,
                               float* __restrict__ H)
{
    int gid = blockIdx.x * 256 + threadIdx.x;   // BB*DS*DI = 65536
    int d = gid & (DI - 1);
    int s = (gid >> 11) & (DS - 1);
    int b = gid >> 15;
    float h = 0.f;
    #pragma unroll
    for (int ch = 0; ch < NCH; ch++) {
        size_t idx = ((size_t)((b * NCH + ch) * DS + s)) * DI + d;
        H[idx] = h;
        h = fmaf(P[idx], h, U[idx]);
    }
}

__global__ __launch_bounds__(256)
void scan_p3_kernel(const bf16* __restrict__ dt,
                    const bf16* __restrict__ xc,
                    const float* __restrict__ dbl,
                    const bf16* __restrict__ xz,
                    const float* __restrict__ A_log,
                    const float* __restrict__ Dp,
                    const float* __restrict__ H,
                    bf16* __restrict__ y)
{
    int gid = blockIdx.x * 256 + threadIdx.x;   // 131072
    int d  = gid & (DI - 1);
    int ch = (gid >> 11) & (NCH - 1);
    int b  = gid >> 16;

    float A2[DS], h[DS];
    size_t hbase = ((size_t)(b * NCH + ch) * DS) * DI + d;
    #pragma unroll
    for (int s = 0; s < DS; s++) {
        A2[s] = -__expf(A_log[d * DS + s]) * LOG2E;
        h[s] = H[hbase + (size_t)s * DI];
    }
    bool fastp = true;
    #pragma unroll
    for (int s = 0; s < DS; s++)
        fastp = fastp && (fabsf(A2[s] - (float)(s + 1) * A2[0]) <= 1e-4f * fabsf(A2[s]));

    float D_d = Dp[d];
    size_t mbase = (size_t)b * LL + ch * CH;
    if (fastp) {
        float A20 = A2[0];
        for (int l = 0; l < CH; l++) {
            size_t m = mbase + l;
            float dtv = __bfloat162float(dt[m * DI + d]);
            float xv  = __bfloat162float(xc[m * DI + d]);
            float dx  = dtv * xv;
            const float4* Bp = (const float4*)(dbl + m * 96 + DTR);
            float4 B0 = Bp[0], B1 = Bp[1], B2 = Bp[2], B3 = Bp[3];
            const float4* Cp = (const float4*)(dbl + m * 96 + DTR + DS);
            float4 C0 = Cp[0], C1 = Cp[1], C2 = Cp[2], C3 = Cp[3];
            float Bv[DS] = {B0.x,B0.y,B0.z,B0.w, B1.x,B1.y,B1.z,B1.w,
                            B2.x,B2.y,B2.z,B2.w, B3.x,B3.y,B3.z,B3.w};
            float Cv[DS] = {C0.x,C0.y,C0.z,C0.w, C1.x,C1.y,C1.z,C1.w,
                            C2.x,C2.y,C2.z,C2.w, C3.x,C3.y,C3.z,C3.w};
            float a1 = exp2f(dtv * A20);
            float as = a1;
            float acc = 0.f;
            #pragma unroll
            for (int s = 0; s < DS; s++) {
                h[s] = fmaf(as, h[s], dx * Bv[s]);
                acc = fmaf(h[s], Cv[s], acc);
                as *= a1;
            }
            float zv = __bfloat162float(xz[m * (2*DI) + DI + d]);
            float yy = fmaf(xv, D_d, acc);
            y[m * DI + d] = __float2bfloat16(yy * (zv / (1.f + __expf(-zv))));
        }
    } else {
        for (int l = 0; l < CH; l++) {
            size_t m = mbase + l;
            float dtv = __bfloat162float(dt[m * DI + d]);
            float xv  = __bfloat162float(xc[m * DI + d]);
            float dx  = dtv * xv;
            const float4* Bp = (const float4*)(dbl + m * 96 + DTR);
            float4 B0 = Bp[0], B1 = Bp[1], B2 = Bp[2], B3 = Bp[3];
            const float4* Cp = (const float4*)(dbl + m * 96 + DTR + DS);
            float4 C0 = Cp[0], C1 = Cp[1], C2 = Cp[2], C3 = Cp[3];
            float Bv[DS] = {B0.x,B0.y,B0.z,B0.w, B1.x,B1.y,B1.z,B1.w,
                            B2.x,B2.y,B2.z,B2.w, B3.x,B3.y,B3.z,B3.w};
            float Cv[DS] = {C0.x,C0.y,C0.z,C0.w, C1.x,C1.y,C1.z,C1.w,
                            C2.x,C2.y,C2.z,C2.w, C3.x,C3.y,C3.z,C3.w};
            float acc = 0.f;
            #pragma unroll
            for (int s = 0; s < DS; s++) {
                float a = exp2f(dtv * A2[s]);
                h[s] = fmaf(a, h[s], dx * Bv[s]);
                acc = fmaf(h[s], Cv[s], acc);
            }
            float zv = __bfloat162float(xz[m * (2*DI) + DI + d]);
            float yy = fmaf(xv, D_d, acc);
            y[m * DI + d] = __float2bfloat16(yy * (zv / (1.f + __expf(-zv))));
        }
    }
}

// ---------------- launcher -------------------------------------------------
extern "C" void kernel_launch(void* const* d_in, const int* in_sizes, int n_in,
                              void* d_out, int out_size)
{
    const float* x      = (const float*)d_in[0];
    const float* ln_g   = (const float*)d_in[1];
    const float* ln_b   = (const float*)d_in[2];
    const float* W_in   = (const float*)d_in[3];
    const float* conv_w = (const float*)d_in[4];
    const float* conv_b = (const float*)d_in[5];
    const float* W_xp   = (const float*)d_in[6];
    const float* W_dt   = (const float*)d_in[7];
    const float* b_dt   = (const float*)d_in[8];
    const float* A_log  = (const float*)d_in[9];
    const float* Dp     = (const float*)d_in[10];
    const float* W_out  = (const float*)d_in[11];
    float* out = (float*)d_out;

    float *dbl, *dblp, *Pb, *Ub, *Hb;
    bf16 *xz, *dtb, *xnb, *xcb, *dtlo, *yb, *Winb, *Wxpb, *Wdtb, *Woutb;
    cudaGetSymbolAddress((void**)&xz,   g_xz);
    cudaGetSymbolAddress((void**)&dbl,  g_dbl);
    cudaGetSymbolAddress((void**)&dblp, g_dblp);
    cudaGetSymbolAddress((void**)&dtb,  g_dt);
    cudaGetSymbolAddress((void**)&xnb,  g_xnb);
    cudaGetSymbolAddress((void**)&xcb,  g_xcb);
    cudaGetSymbolAddress((void**)&dtlo, g_dtlo);
    cudaGetSymbolAddress((void**)&yb,   g_yb);
    cudaGetSymbolAddress((void**)&Winb, g_Winb);
    cudaGetSymbolAddress((void**)&Wxpb, g_Wxpb);
    cudaGetSymbolAddress((void**)&Wdtb, g_Wdtb);
    cudaGetSymbolAddress((void**)&Woutb,g_Woutb);
    cudaGetSymbolAddress((void**)&Pb,   g_P);
    cudaGetSymbolAddress((void**)&Ub,   g_U);
    cudaGetSymbolAddress((void**)&Hb,   g_H);

    constexpr int SM_MMA = 3 * (128 + 128) * 72 * 2;          // 110592 (108 KB)
    constexpr int SM_64  = (64 + 128) * SPAD * 2 * STAGES;    // 46080
    cudaFuncSetAttribute(mma_gemm_kernel<1>, cudaFuncAttributeMaxDynamicSharedMemorySize, SM_MMA);
    cudaFuncSetAttribute(mma_gemm_kernel<2>, cudaFuncAttributeMaxDynamicSharedMemorySize, SM_MMA);
    cudaFuncSetAttribute(mma_gemm_kernel<3>, cudaFuncAttributeMaxDynamicSharedMemorySize, SM_MMA);
    cudaFuncSetAttribute(hgemm_kernel<64,128,2,4>, cudaFuncAttributeMaxDynamicSharedMemorySize, SM_64);

    const int nWxp = 96*DI, nWdt = DI*DTR, nWout = DM*DI;

    // 1. W_in -> bf16
    f2bf_kernel<<<((2*DI*DM)/4 + 255)/256, 256>>>(W_in,  Winb, 2*DI*DM);
    // 2. LayerNorm -> bf16
    layernorm_kernel<<<MM, 256>>>(x, ln_g, ln_b, xnb);
    // 3. W_xp + W_dt + W_out -> bf16 (one launch)
    f2bf3_kernel<<<(((nWxp+nWdt+nWout)/4) + 255)/256, 256>>>(
        W_xp, Wxpb, nWxp, W_dt, Wdtb, nWdt, W_out, Woutb, nWout);
    // 4. xz = xn @ W_in^T -> bf16  [8192 x 4096], K=1024   <-- PROFILED (#4)
    mma_gemm_kernel<3><<<dim3(4096/128, MM/128), 128, SM_MMA>>>(
        xnb, DM, Winb, DM, xz, 2*DI, DM, nullptr);
    // 5. causal conv + silu -> xcb (bf16 in/out)
    conv_silu_kernel<<<(MM*DI/4)/256, 256>>>(xz, conv_w, conv_b, xcb);
    // 6. dbl partials = xc @ W_xp^T, split-K x4
    hgemm_kernel<64,128,2,4><<<dim3(1, MM/64, 4), 256, SM_64>>>(
        xcb, DI, Wxpb, DI, dblp, 96, 96, DI/4, DI/4, (size_t)MM*96);
    // 7. reduce partials -> dbl fp32 + dtlo bf16
    dbl_reduce_kernel<<<(MM*96)/256, 256>>>(dblp, dbl, dtlo);
    // 8. dt = softplus(dt_lo @ W_dt^T + b_dt) -> bf16
    mma_gemm_kernel<2><<<dim3(DI/128, MM/128), 128, SM_MMA>>>(
        dtlo, DTR, Wdtb, DTR, dtb, DI, DTR, b_dt);
    // 9-11. chunked selective scan
    scan_p1_kernel<<<(BB*NCH*DI)/256, 256>>>(dtb, xcb, dbl, A_log, Pb, Ub);
    scan_p2_kernel<<<(BB*DS*DI)/256, 256>>>(Pb, Ub, Hb);
    scan_p3_kernel<<<(BB*NCH*DI)/256, 256>>>(dtb, xcb, dbl, xz, A_log, Dp, Hb, yb);
    // 12. out = x + y @ W_out^T  [8192 x 1024], K=2048
    mma_gemm_kernel<1><<<dim3(DM/128, MM/128), 128, SM_MMA>>>(
        yb, DI, Woutb, DI, out, DM, DI, x);
}